// round 1
// baseline (speedup 1.0000x reference)
#include <cuda_runtime.h>

#define D 128
#define ROWS_PAD 50048           // 782 * 64, covers grid padding
#define HASH_SIZE (1u << 21)     // 2M entries, load factor ~0.38

// ---------------- device-global scratch (no allocations allowed) ------------
__device__ unsigned long long g_hash[HASH_SIZE];      // 16 MB
__device__ float g_h[(size_t)ROWS_PAD * D];           // 25.6 MB, (1+a)*nfeats + agg
__device__ int g_idx64;                                // 1 if indices are int64

// ---------------- packed f32x2 helpers (Blackwell FFMA2) --------------------
__device__ __forceinline__ unsigned long long ffma2(unsigned long long a,
                                                    unsigned long long b,
                                                    unsigned long long c) {
    unsigned long long d;
    asm("fma.rn.f32x2 %0, %1, %2, %3;" : "=l"(d) : "l"(a), "l"(b), "l"(c));
    return d;
}
__device__ __forceinline__ unsigned long long pack2(float lo, float hi) {
    unsigned long long r;
    asm("mov.b64 %0, {%1, %2};" : "=l"(r) : "f"(lo), "f"(hi));
    return r;
}
__device__ __forceinline__ void unpack2(unsigned long long v, float& lo, float& hi) {
    asm("mov.b64 {%0, %1}, %2;" : "=f"(lo), "=f"(hi) : "l"(v));
}

// ---------------- phase 0: index dtype detection ----------------------------
// int64 values < 50000 -> every odd 32-bit word of the first 8 elements is 0.
// For int32 data those words are independent random values in [0,50000):
// P(all zero) ~ (2e-5)^8 ~ 0.
__global__ void k_detect(const unsigned int* __restrict__ src) {
    if (blockIdx.x == 0 && threadIdx.x == 0) {
        int is64 = 1;
#pragma unroll
        for (int i = 0; i < 8; i++)
            if (src[2 * i + 1] != 0u) is64 = 0;
        g_idx64 = is64;
    }
}

// ---------------- phase 1: clear hash, init h = (1+alpha)*nfeats ------------
__global__ void k_clear_hash() {
    unsigned int i = blockIdx.x * blockDim.x + threadIdx.x;
    if (i < HASH_SIZE) g_hash[i] = ~0ull;
}

__global__ void k_init_h(const float4* __restrict__ nf,
                         const float* __restrict__ alpha, int n4) {
    int i = blockIdx.x * blockDim.x + threadIdx.x;
    if (i >= n4) return;
    float s = 1.0f + alpha[0];
    float4 v = nf[i];
    v.x *= s; v.y *= s; v.z *= s; v.w *= s;
    ((float4*)g_h)[i] = v;
}

// ---------------- phase 2: dedup + gather + scatter-add, warp per edge ------
__global__ void __launch_bounds__(256)
k_edges(const void* __restrict__ srcp, const void* __restrict__ dstp,
        const float* __restrict__ nfeats, int nE) {
    int e = (int)((blockIdx.x * 256u + threadIdx.x) >> 5);
    int lane = threadIdx.x & 31;
    if (e >= nE) return;

    int s, d;
    if (g_idx64) {
        s = (int)((const long long*)srcp)[e];
        d = (int)((const long long*)dstp)[e];
    } else {
        s = ((const int*)srcp)[e];
        d = ((const int*)dstp)[e];
    }

    int keep = 0;
    if (lane == 0) {
        unsigned long long key =
            ((unsigned long long)(unsigned)s << 32) | (unsigned)d;
        unsigned long long hv = key * 0x9E3779B97F4A7C15ull;
        unsigned int slot = (unsigned int)(hv >> 43) & (HASH_SIZE - 1);
        for (;;) {
            unsigned long long prev = atomicCAS(&g_hash[slot], ~0ull, key);
            if (prev == ~0ull) { keep = 1; break; }   // claimed: representative
            if (prev == key) break;                    // duplicate: drop
            slot = (slot + 1) & (HASH_SIZE - 1);
        }
    }
    keep = __shfl_sync(0xffffffffu, keep, 0);
    if (!keep) return;

    // 32 lanes x float4 = full 128-float row
    float4 v = ((const float4*)(nfeats + (size_t)s * D))[lane];
    float* p = &g_h[(size_t)d * D + lane * 4];
    asm volatile("red.global.add.v4.f32 [%0], {%1,%2,%3,%4};"
                 :: "l"(p), "f"(v.x), "f"(v.y), "f"(v.z), "f"(v.w)
                 : "memory");
}

// ---------------- phase 3: fused relu(h@W1+b1)@W2+b2 ------------------------
// Block: 256 threads = 32 (cols) x 8 (row groups). 64 rows/block.
// Each thread: 8 rows x 4 cols, accumulators as 2x f32x2.
// smem: W1(64K) + W2(64K) + Htile(32K) + H1tile(32K) = 192 KB.
__global__ void __launch_bounds__(256, 1)
k_mlp(const float* __restrict__ W1, const float* __restrict__ b1,
      const float* __restrict__ W2, const float* __restrict__ b2,
      float* __restrict__ out, int nrows) {
    extern __shared__ float smem[];
    float* sW1 = smem;                 // 128*128
    float* sW2 = smem + 16384;         // 128*128
    float* sH  = smem + 32768;         // 64*128
    float* sH1 = smem + 32768 + 8192;  // 64*128

    int tid = threadIdx.x;
    int x = tid & 31;        // col group: cols [4x, 4x+4)
    int y = tid >> 5;        // row group: rows [8y, 8y+8) within tile
    int row0 = blockIdx.x * 64;

    // cooperative loads
    for (int i = tid; i < 4096; i += 256) {
        ((float4*)sW1)[i] = ((const float4*)W1)[i];
        ((float4*)sW2)[i] = ((const float4*)W2)[i];
    }
    {
        const float4* gh4 = (const float4*)(g_h + (size_t)row0 * D);
        for (int i = tid; i < 2048; i += 256) ((float4*)sH)[i] = gh4[i];
    }
    __syncthreads();

    unsigned long long a01[8], a23[8];

    // ---- layer 1: relu(h @ W1 + b1) -> sH1 ----
    {
        float4 bv = *(const float4*)(b1 + x * 4);
        unsigned long long i01 = pack2(bv.x, bv.y), i23 = pack2(bv.z, bv.w);
#pragma unroll
        for (int i = 0; i < 8; i++) { a01[i] = i01; a23[i] = i23; }

        const float* hrow = sH + y * 8 * D;
#pragma unroll 4
        for (int k = 0; k < D; k++) {
            ulonglong2 wv = *(const ulonglong2*)(sW1 + k * D + x * 4);
#pragma unroll
            for (int i = 0; i < 8; i++) {
                float hk = hrow[i * D + k];                 // warp broadcast
                unsigned long long h2 = pack2(hk, hk);
                a01[i] = ffma2(h2, wv.x, a01[i]);
                a23[i] = ffma2(h2, wv.y, a23[i]);
            }
        }
#pragma unroll
        for (int i = 0; i < 8; i++) {
            float f0, f1, f2, f3;
            unpack2(a01[i], f0, f1); unpack2(a23[i], f2, f3);
            float4 v = make_float4(fmaxf(f0, 0.f), fmaxf(f1, 0.f),
                                   fmaxf(f2, 0.f), fmaxf(f3, 0.f));
            *(float4*)(sH1 + (y * 8 + i) * D + x * 4) = v;
        }
    }
    // Each warp (fixed y) reads back exactly the rows it wrote -> warp sync only.
    __syncwarp();

    // ---- layer 2: h1 @ W2 + b2 -> out ----
    {
        float4 bv = *(const float4*)(b2 + x * 4);
        unsigned long long i01 = pack2(bv.x, bv.y), i23 = pack2(bv.z, bv.w);
#pragma unroll
        for (int i = 0; i < 8; i++) { a01[i] = i01; a23[i] = i23; }

        const float* hrow = sH1 + y * 8 * D;
#pragma unroll 4
        for (int k = 0; k < D; k++) {
            ulonglong2 wv = *(const ulonglong2*)(sW2 + k * D + x * 4);
#pragma unroll
            for (int i = 0; i < 8; i++) {
                float hk = hrow[i * D + k];
                unsigned long long h2 = pack2(hk, hk);
                a01[i] = ffma2(h2, wv.x, a01[i]);
                a23[i] = ffma2(h2, wv.y, a23[i]);
            }
        }
#pragma unroll
        for (int i = 0; i < 8; i++) {
            int gr = row0 + y * 8 + i;
            if (gr < nrows) {
                float f0, f1, f2, f3;
                unpack2(a01[i], f0, f1); unpack2(a23[i], f2, f3);
                *(float4*)(out + (size_t)gr * D + x * 4) =
                    make_float4(f0, f1, f2, f3);
            }
        }
    }
}

// ---------------- launch ----------------------------------------------------
extern "C" void kernel_launch(void* const* d_in, const int* in_sizes, int n_in,
                              void* d_out, int out_size) {
    const float* nfeats = (const float*)d_in[0];
    const void*  src    = d_in[1];
    const void*  dst    = d_in[2];
    const float* W1     = (const float*)d_in[3];
    const float* b1     = (const float*)d_in[4];
    const float* W2     = (const float*)d_in[5];
    const float* b2     = (const float*)d_in[6];
    const float* alpha  = (const float*)d_in[7];
    float* out = (float*)d_out;

    int nE    = in_sizes[1];
    int nrows = in_sizes[0] / D;

    k_detect<<<1, 32>>>((const unsigned int*)src);
    k_clear_hash<<<(HASH_SIZE + 255) / 256, 256>>>();

    int n4 = nrows * (D / 4);
    k_init_h<<<(n4 + 255) / 256, 256>>>((const float4*)nfeats, alpha, n4);

    k_edges<<<(nE + 7) / 8, 256>>>(src, dst, nfeats, nE);

    cudaFuncSetAttribute(k_mlp, cudaFuncAttributeMaxDynamicSharedMemorySize,
                         196608);
    int nblk = (nrows + 63) / 64;
    k_mlp<<<nblk, 256, 196608>>>(W1, b1, W2, b2, out, nrows);
}

// round 2
// speedup vs baseline: 1.0881x; 1.0881x over previous
#include <cuda_runtime.h>

#define D 128
#define NMAX 50048               // 782 * 64, covers MLP grid padding
#define EMAX 1048576             // >= 800000 edges
#define HASH_SIZE (1u << 21)     // 2M entries, load factor ~0.38

// ---------------- device-global scratch (no allocations allowed) ------------
__device__ unsigned long long g_hash[HASH_SIZE];      // 16 MB
__device__ float g_h[(size_t)NMAX * D];               // 25.6 MB (zero-init BSS)
__device__ int g_count[NMAX];
__device__ int g_offset[NMAX + 1];
__device__ int g_cursor[NMAX];
__device__ int g_bucket[EMAX];                        // src ids grouped by dst
__device__ unsigned char g_keep[EMAX];
__device__ int g_idx64;                                // 1 if indices are int64

// ---------------- packed f32x2 helpers (Blackwell FFMA2) --------------------
__device__ __forceinline__ unsigned long long ffma2(unsigned long long a,
                                                    unsigned long long b,
                                                    unsigned long long c) {
    unsigned long long d;
    asm("fma.rn.f32x2 %0, %1, %2, %3;" : "=l"(d) : "l"(a), "l"(b), "l"(c));
    return d;
}
__device__ __forceinline__ unsigned long long pack2(float lo, float hi) {
    unsigned long long r;
    asm("mov.b64 %0, {%1, %2};" : "=l"(r) : "f"(lo), "f"(hi));
    return r;
}
__device__ __forceinline__ void unpack2(unsigned long long v, float& lo, float& hi) {
    asm("mov.b64 {%0, %1}, %2;" : "=f"(lo), "=f"(hi) : "l"(v));
}

__device__ __forceinline__ void load_sd(const void* srcp, const void* dstp,
                                        int e, int& s, int& d) {
    if (g_idx64) {
        s = (int)((const long long*)srcp)[e];
        d = (int)((const long long*)dstp)[e];
    } else {
        s = ((const int*)srcp)[e];
        d = ((const int*)dstp)[e];
    }
}

// ---- phase 0: clear hash, zero counts, detect index dtype ------------------
__global__ void k_setup(const unsigned int* __restrict__ src) {
    unsigned int i = blockIdx.x * blockDim.x + threadIdx.x;
    if (i < HASH_SIZE) g_hash[i] = ~0ull;
    if (i < NMAX) g_count[i] = 0;
    if (i == 0) {
        // int64 values < 50000 -> odd 32-bit words of first 8 elems all zero
        int is64 = 1;
#pragma unroll
        for (int k = 0; k < 8; k++)
            if (src[2 * k + 1] != 0u) is64 = 0;
        g_idx64 = is64;
    }
}

// ---- phase 1: dedup (thread per edge) + dst histogram ----------------------
__global__ void __launch_bounds__(256)
k_dedup(const void* __restrict__ srcp, const void* __restrict__ dstp, int nE) {
    int e = blockIdx.x * blockDim.x + threadIdx.x;
    if (e >= nE) return;
    int s, d;
    load_sd(srcp, dstp, e, s, d);

    unsigned long long key =
        ((unsigned long long)(unsigned)s << 32) | (unsigned)d;
    unsigned long long hv = key * 0x9E3779B97F4A7C15ull;
    unsigned int slot = (unsigned int)(hv >> 43) & (HASH_SIZE - 1);
    int keep = 0;
    for (;;) {
        unsigned long long prev = atomicCAS(&g_hash[slot], ~0ull, key);
        if (prev == ~0ull) { keep = 1; break; }   // claimed: representative
        if (prev == key) break;                    // duplicate: drop
        slot = (slot + 1) & (HASH_SIZE - 1);
    }
    g_keep[e] = (unsigned char)keep;
    if (keep) atomicAdd(&g_count[d], 1);
}

// ---- phase 2: exclusive scan of counts -> offsets (one block) --------------
__global__ void k_scan(int n) {
    __shared__ int part[1024];
    int t = threadIdx.x;
    int C = (n + 1023) >> 10;
    int base = t * C;
    int s = 0;
    for (int i = 0; i < C; i++) {
        int id = base + i;
        if (id < n) s += g_count[id];
    }
    part[t] = s;
    __syncthreads();
    for (int off = 1; off < 1024; off <<= 1) {
        int v = (t >= off) ? part[t - off] : 0;
        __syncthreads();
        part[t] += v;
        __syncthreads();
    }
    int run = (t > 0) ? part[t - 1] : 0;
    for (int i = 0; i < C; i++) {
        int id = base + i;
        if (id < n) {
            g_offset[id] = run;
            g_cursor[id] = run;
            run += g_count[id];
        }
    }
    if (t == 1023) g_offset[n] = part[1023];
}

// ---- phase 3: scatter kept edges' src ids into per-dst buckets -------------
__global__ void __launch_bounds__(256)
k_fill(const void* __restrict__ srcp, const void* __restrict__ dstp, int nE) {
    int e = blockIdx.x * blockDim.x + threadIdx.x;
    if (e >= nE) return;
    if (!g_keep[e]) return;
    int s, d;
    load_sd(srcp, dstp, e, s, d);
    int pos = atomicAdd(&g_cursor[d], 1);
    g_bucket[pos] = s;
}

// ---- phase 4: warp-per-dst gather-sum + (1+alpha)*x fused ------------------
__global__ void __launch_bounds__(256)
k_agg(const float* __restrict__ nfeats, const float* __restrict__ alpha,
      int nrows) {
    int w = (int)((blockIdx.x * 256u + threadIdx.x) >> 5);
    int lane = threadIdx.x & 31;
    if (w >= nrows) return;

    const float4* nf4 = (const float4*)nfeats;
    float sc = 1.0f + alpha[0];
    float4 a = nf4[(size_t)w * 32 + lane];
    float4 acc = make_float4(a.x * sc, a.y * sc, a.z * sc, a.w * sc);

    int j = g_offset[w];
    int end = g_offset[w + 1];
    // unrolled gather: 4 independent row loads in flight per iteration
    for (; j + 4 <= end; j += 4) {
        int s0 = g_bucket[j], s1 = g_bucket[j + 1];
        int s2 = g_bucket[j + 2], s3 = g_bucket[j + 3];
        float4 v0 = nf4[(size_t)s0 * 32 + lane];
        float4 v1 = nf4[(size_t)s1 * 32 + lane];
        float4 v2 = nf4[(size_t)s2 * 32 + lane];
        float4 v3 = nf4[(size_t)s3 * 32 + lane];
        acc.x += (v0.x + v1.x) + (v2.x + v3.x);
        acc.y += (v0.y + v1.y) + (v2.y + v3.y);
        acc.z += (v0.z + v1.z) + (v2.z + v3.z);
        acc.w += (v0.w + v1.w) + (v2.w + v3.w);
    }
    for (; j < end; j++) {
        int s0 = g_bucket[j];
        float4 v0 = nf4[(size_t)s0 * 32 + lane];
        acc.x += v0.x; acc.y += v0.y; acc.z += v0.z; acc.w += v0.w;
    }
    ((float4*)g_h)[(size_t)w * 32 + lane] = acc;
}

// ---- phase 5: fused relu(h@W1+b1)@W2+b2 ------------------------------------
// Block: 256 threads = 32 (cols) x 8 (row groups). 64 rows/block.
// Each thread: 8 rows x 4 cols, accumulators as 2x f32x2.
__global__ void __launch_bounds__(256, 1)
k_mlp(const float* __restrict__ W1, const float* __restrict__ b1,
      const float* __restrict__ W2, const float* __restrict__ b2,
      float* __restrict__ out, int nrows) {
    extern __shared__ float smem[];
    float* sW1 = smem;                 // 128*128
    float* sW2 = smem + 16384;         // 128*128
    float* sH  = smem + 32768;         // 64*128
    float* sH1 = smem + 32768 + 8192;  // 64*128

    int tid = threadIdx.x;
    int x = tid & 31;        // col group: cols [4x, 4x+4)
    int y = tid >> 5;        // row group: rows [8y, 8y+8) within tile
    int row0 = blockIdx.x * 64;

    for (int i = tid; i < 4096; i += 256) {
        ((float4*)sW1)[i] = ((const float4*)W1)[i];
        ((float4*)sW2)[i] = ((const float4*)W2)[i];
    }
    {
        const float4* gh4 = (const float4*)(g_h + (size_t)row0 * D);
        for (int i = tid; i < 2048; i += 256) ((float4*)sH)[i] = gh4[i];
    }
    __syncthreads();

    unsigned long long a01[8], a23[8];

    // ---- layer 1: relu(h @ W1 + b1) -> sH1 ----
    {
        float4 bv = *(const float4*)(b1 + x * 4);
        unsigned long long i01 = pack2(bv.x, bv.y), i23 = pack2(bv.z, bv.w);
#pragma unroll
        for (int i = 0; i < 8; i++) { a01[i] = i01; a23[i] = i23; }

        const float* hrow = sH + y * 8 * D;
#pragma unroll 4
        for (int k = 0; k < D; k++) {
            ulonglong2 wv = *(const ulonglong2*)(sW1 + k * D + x * 4);
#pragma unroll
            for (int i = 0; i < 8; i++) {
                float hk = hrow[i * D + k];
                unsigned long long h2 = pack2(hk, hk);
                a01[i] = ffma2(h2, wv.x, a01[i]);
                a23[i] = ffma2(h2, wv.y, a23[i]);
            }
        }
#pragma unroll
        for (int i = 0; i < 8; i++) {
            float f0, f1, f2, f3;
            unpack2(a01[i], f0, f1); unpack2(a23[i], f2, f3);
            float4 v = make_float4(fmaxf(f0, 0.f), fmaxf(f1, 0.f),
                                   fmaxf(f2, 0.f), fmaxf(f3, 0.f));
            *(float4*)(sH1 + (y * 8 + i) * D + x * 4) = v;
        }
    }
    // Each warp (fixed y) reads back exactly the rows it wrote.
    __syncwarp();

    // ---- layer 2: h1 @ W2 + b2 -> out ----
    {
        float4 bv = *(const float4*)(b2 + x * 4);
        unsigned long long i01 = pack2(bv.x, bv.y), i23 = pack2(bv.z, bv.w);
#pragma unroll
        for (int i = 0; i < 8; i++) { a01[i] = i01; a23[i] = i23; }

        const float* hrow = sH1 + y * 8 * D;
#pragma unroll 4
        for (int k = 0; k < D; k++) {
            ulonglong2 wv = *(const ulonglong2*)(sW2 + k * D + x * 4);
#pragma unroll
            for (int i = 0; i < 8; i++) {
                float hk = hrow[i * D + k];
                unsigned long long h2 = pack2(hk, hk);
                a01[i] = ffma2(h2, wv.x, a01[i]);
                a23[i] = ffma2(h2, wv.y, a23[i]);
            }
        }
#pragma unroll
        for (int i = 0; i < 8; i++) {
            int gr = row0 + y * 8 + i;
            if (gr < nrows) {
                float f0, f1, f2, f3;
                unpack2(a01[i], f0, f1); unpack2(a23[i], f2, f3);
                *(float4*)(out + (size_t)gr * D + x * 4) =
                    make_float4(f0, f1, f2, f3);
            }
        }
    }
}

// ---------------- launch ----------------------------------------------------
extern "C" void kernel_launch(void* const* d_in, const int* in_sizes, int n_in,
                              void* d_out, int out_size) {
    const float* nfeats = (const float*)d_in[0];
    const void*  src    = d_in[1];
    const void*  dst    = d_in[2];
    const float* W1     = (const float*)d_in[3];
    const float* b1     = (const float*)d_in[4];
    const float* W2     = (const float*)d_in[5];
    const float* b2     = (const float*)d_in[6];
    const float* alpha  = (const float*)d_in[7];
    float* out = (float*)d_out;

    int nE    = in_sizes[1];
    int nrows = in_sizes[0] / D;

    k_setup<<<(HASH_SIZE + 255) / 256, 256>>>((const unsigned int*)src);
    k_dedup<<<(nE + 255) / 256, 256>>>(src, dst, nE);
    k_scan<<<1, 1024>>>(nrows);
    k_fill<<<(nE + 255) / 256, 256>>>(src, dst, nE);
    k_agg<<<(nrows + 7) / 8, 256>>>(nfeats, alpha, nrows);

    cudaFuncSetAttribute(k_mlp, cudaFuncAttributeMaxDynamicSharedMemorySize,
                         196608);
    int nblk = (nrows + 63) / 64;
    k_mlp<<<nblk, 256, 196608>>>(W1, b1, W2, b2, out, nrows);
}

// round 3
// speedup vs baseline: 1.6301x; 1.4982x over previous
#include <cuda_runtime.h>

#define D 128
#define NMAX 50048               // 782 * 64, covers MLP grid padding
#define PAD 64                   // bucket slots per dst
#define HASH_SIZE (1u << 21)     // 2M entries, load factor ~0.38
#define OVF_MAX 4096

// ---------------- device-global scratch (no allocations allowed) ------------
__device__ unsigned long long g_hash[HASH_SIZE];      // 16 MB
__device__ float g_h[(size_t)NMAX * D];               // 25.6 MB
__device__ int g_cnt[NMAX];
__device__ int g_bucket[(size_t)NMAX * PAD];          // 12.8 MB
__device__ int g_ovf[OVF_MAX * 2];                    // spill (s,d) pairs
__device__ int g_ovf_cnt;
__device__ int g_idx64;                                // 1 if indices are int64

// ---------------- packed f32x2 helpers (Blackwell FFMA2) --------------------
__device__ __forceinline__ unsigned long long ffma2(unsigned long long a,
                                                    unsigned long long b,
                                                    unsigned long long c) {
    unsigned long long d;
    asm("fma.rn.f32x2 %0, %1, %2, %3;" : "=l"(d) : "l"(a), "l"(b), "l"(c));
    return d;
}
__device__ __forceinline__ unsigned long long pack2(float lo, float hi) {
    unsigned long long r;
    asm("mov.b64 %0, {%1, %2};" : "=l"(r) : "f"(lo), "f"(hi));
    return r;
}
__device__ __forceinline__ void unpack2(unsigned long long v, float& lo, float& hi) {
    asm("mov.b64 {%0, %1}, %2;" : "=f"(lo), "=f"(hi) : "l"(v));
}

// ---- phase 0: clear hash (128-bit stores), zero counts, detect dtype -------
__global__ void k_setup(const unsigned int* __restrict__ src) {
    unsigned int i = blockIdx.x * blockDim.x + threadIdx.x;
    if (i < HASH_SIZE / 2) {
        ulonglong2 v; v.x = ~0ull; v.y = ~0ull;
        ((ulonglong2*)g_hash)[i] = v;
    }
    if (i < NMAX) g_cnt[i] = 0;
    if (i == 0) {
        g_ovf_cnt = 0;
        // int64 values < 50000 -> odd 32-bit words of first 8 elems all zero
        int is64 = 1;
#pragma unroll
        for (int k = 0; k < 8; k++)
            if (src[2 * k + 1] != 0u) is64 = 0;
        g_idx64 = is64;
    }
}

// ---- phase 1: fused dedup + bucket fill (thread per edge) ------------------
__global__ void __launch_bounds__(256)
k_dedup_fill(const void* __restrict__ srcp, const void* __restrict__ dstp,
             int nE) {
    int e = blockIdx.x * blockDim.x + threadIdx.x;
    if (e >= nE) return;
    int s, d;
    if (g_idx64) {
        s = (int)((const long long*)srcp)[e];
        d = (int)((const long long*)dstp)[e];
    } else {
        s = ((const int*)srcp)[e];
        d = ((const int*)dstp)[e];
    }

    unsigned long long key =
        ((unsigned long long)(unsigned)s << 32) | (unsigned)d;
    unsigned long long hv = key * 0x9E3779B97F4A7C15ull;
    unsigned int slot = (unsigned int)(hv >> 43) & (HASH_SIZE - 1);
    for (;;) {
        unsigned long long prev = atomicCAS(&g_hash[slot], ~0ull, key);
        if (prev == ~0ull) break;                  // claimed: representative
        if (prev == key) return;                   // duplicate: drop
        slot = (slot + 1) & (HASH_SIZE - 1);
    }
    int pos = atomicAdd(&g_cnt[d], 1);
    if (pos < PAD) {
        g_bucket[(size_t)d * PAD + pos] = s;
    } else {                                       // ~never taken
        int o = atomicAdd(&g_ovf_cnt, 1);
        if (o < OVF_MAX) { g_ovf[2 * o] = s; g_ovf[2 * o + 1] = d; }
    }
}

// ---- phase 2: warp-per-dst gather-sum + (1+alpha)*x fused ------------------
__global__ void __launch_bounds__(256)
k_agg(const float* __restrict__ nfeats, const float* __restrict__ alpha,
      int nrows) {
    int w = (int)((blockIdx.x * 256u + threadIdx.x) >> 5);
    int lane = threadIdx.x & 31;
    if (w >= nrows) return;

    const float4* nf4 = (const float4*)nfeats;
    float sc = 1.0f + alpha[0];
    float4 a = nf4[(size_t)w * 32 + lane];
    float4 acc = make_float4(a.x * sc, a.y * sc, a.z * sc, a.w * sc);

    int cnt = g_cnt[w];
    if (cnt > PAD) cnt = PAD;
    const int* bk = &g_bucket[(size_t)w * PAD];

    int j = 0;
    for (; j + 4 <= cnt; j += 4) {
        int s0 = bk[j], s1 = bk[j + 1], s2 = bk[j + 2], s3 = bk[j + 3];
        float4 v0 = nf4[(size_t)s0 * 32 + lane];
        float4 v1 = nf4[(size_t)s1 * 32 + lane];
        float4 v2 = nf4[(size_t)s2 * 32 + lane];
        float4 v3 = nf4[(size_t)s3 * 32 + lane];
        acc.x += (v0.x + v1.x) + (v2.x + v3.x);
        acc.y += (v0.y + v1.y) + (v2.y + v3.y);
        acc.z += (v0.z + v1.z) + (v2.z + v3.z);
        acc.w += (v0.w + v1.w) + (v2.w + v3.w);
    }
    for (; j < cnt; j++) {
        int s0 = bk[j];
        float4 v0 = nf4[(size_t)s0 * 32 + lane];
        acc.x += v0.x; acc.y += v0.y; acc.z += v0.z; acc.w += v0.w;
    }
    ((float4*)g_h)[(size_t)w * 32 + lane] = acc;
}

// ---- phase 2b: apply spilled edges (normally zero work) --------------------
__global__ void k_overflow(const float* __restrict__ nfeats) {
    int n = g_ovf_cnt;
    if (n > OVF_MAX) n = OVF_MAX;
    int w = (int)((blockIdx.x * blockDim.x + threadIdx.x) >> 5);
    int lane = threadIdx.x & 31;
    if (w >= n) return;
    int s = g_ovf[2 * w], d = g_ovf[2 * w + 1];
    float4 v = ((const float4*)(nfeats + (size_t)s * D))[lane];
    float* p = &g_h[(size_t)d * D + lane * 4];
    asm volatile("red.global.add.v4.f32 [%0], {%1,%2,%3,%4};"
                 :: "l"(p), "f"(v.x), "f"(v.y), "f"(v.z), "f"(v.w)
                 : "memory");
}

// ---- phase 3: fused relu(h@W1+b1)@W2+b2 ------------------------------------
// Block: 256 threads = 32 (cols) x 8 (row groups). 64 rows/block.
// Each thread: 8 rows x 4 cols, accumulators as 2x f32x2.
__global__ void __launch_bounds__(256, 1)
k_mlp(const float* __restrict__ W1, const float* __restrict__ b1,
      const float* __restrict__ W2, const float* __restrict__ b2,
      float* __restrict__ out, int nrows) {
    extern __shared__ float smem[];
    float* sW1 = smem;                 // 128*128
    float* sW2 = smem + 16384;         // 128*128
    float* sH  = smem + 32768;         // 64*128
    float* sH1 = smem + 32768 + 8192;  // 64*128

    int tid = threadIdx.x;
    int x = tid & 31;        // col group: cols [4x, 4x+4)
    int y = tid >> 5;        // row group: rows [8y, 8y+8) within tile
    int row0 = blockIdx.x * 64;

    for (int i = tid; i < 4096; i += 256) {
        ((float4*)sW1)[i] = ((const float4*)W1)[i];
        ((float4*)sW2)[i] = ((const float4*)W2)[i];
    }
    {
        const float4* gh4 = (const float4*)(g_h + (size_t)row0 * D);
        for (int i = tid; i < 2048; i += 256) ((float4*)sH)[i] = gh4[i];
    }
    __syncthreads();

    unsigned long long a01[8], a23[8];

    // ---- layer 1: relu(h @ W1 + b1) -> sH1 ----
    {
        float4 bv = *(const float4*)(b1 + x * 4);
        unsigned long long i01 = pack2(bv.x, bv.y), i23 = pack2(bv.z, bv.w);
#pragma unroll
        for (int i = 0; i < 8; i++) { a01[i] = i01; a23[i] = i23; }

        const float* hrow = sH + y * 8 * D;
#pragma unroll 2
        for (int k0 = 0; k0 < D; k0 += 4) {
            float4 h4[8];
#pragma unroll
            for (int i = 0; i < 8; i++)
                h4[i] = *(const float4*)(hrow + i * D + k0);
#pragma unroll
            for (int kk = 0; kk < 4; kk++) {
                ulonglong2 wv =
                    *(const ulonglong2*)(sW1 + (k0 + kk) * D + x * 4);
#pragma unroll
                for (int i = 0; i < 8; i++) {
                    float hk = (&h4[i].x)[kk];
                    unsigned long long h2 = pack2(hk, hk);
                    a01[i] = ffma2(h2, wv.x, a01[i]);
                    a23[i] = ffma2(h2, wv.y, a23[i]);
                }
            }
        }
#pragma unroll
        for (int i = 0; i < 8; i++) {
            float f0, f1, f2, f3;
            unpack2(a01[i], f0, f1); unpack2(a23[i], f2, f3);
            float4 v = make_float4(fmaxf(f0, 0.f), fmaxf(f1, 0.f),
                                   fmaxf(f2, 0.f), fmaxf(f3, 0.f));
            *(float4*)(sH1 + (y * 8 + i) * D + x * 4) = v;
        }
    }
    // Each warp (fixed y) reads back exactly the rows it wrote.
    __syncwarp();

    // ---- layer 2: h1 @ W2 + b2 -> out ----
    {
        float4 bv = *(const float4*)(b2 + x * 4);
        unsigned long long i01 = pack2(bv.x, bv.y), i23 = pack2(bv.z, bv.w);
#pragma unroll
        for (int i = 0; i < 8; i++) { a01[i] = i01; a23[i] = i23; }

        const float* hrow = sH1 + y * 8 * D;
#pragma unroll 2
        for (int k0 = 0; k0 < D; k0 += 4) {
            float4 h4[8];
#pragma unroll
            for (int i = 0; i < 8; i++)
                h4[i] = *(const float4*)(hrow + i * D + k0);
#pragma unroll
            for (int kk = 0; kk < 4; kk++) {
                ulonglong2 wv =
                    *(const ulonglong2*)(sW2 + (k0 + kk) * D + x * 4);
#pragma unroll
                for (int i = 0; i < 8; i++) {
                    float hk = (&h4[i].x)[kk];
                    unsigned long long h2 = pack2(hk, hk);
                    a01[i] = ffma2(h2, wv.x, a01[i]);
                    a23[i] = ffma2(h2, wv.y, a23[i]);
                }
            }
        }
#pragma unroll
        for (int i = 0; i < 8; i++) {
            int gr = row0 + y * 8 + i;
            if (gr < nrows) {
                float f0, f1, f2, f3;
                unpack2(a01[i], f0, f1); unpack2(a23[i], f2, f3);
                *(float4*)(out + (size_t)gr * D + x * 4) =
                    make_float4(f0, f1, f2, f3);
            }
        }
    }
}

// ---------------- launch ----------------------------------------------------
extern "C" void kernel_launch(void* const* d_in, const int* in_sizes, int n_in,
                              void* d_out, int out_size) {
    const float* nfeats = (const float*)d_in[0];
    const void*  src    = d_in[1];
    const void*  dst    = d_in[2];
    const float* W1     = (const float*)d_in[3];
    const float* b1     = (const float*)d_in[4];
    const float* W2     = (const float*)d_in[5];
    const float* b2     = (const float*)d_in[6];
    const float* alpha  = (const float*)d_in[7];
    float* out = (float*)d_out;

    int nE    = in_sizes[1];
    int nrows = in_sizes[0] / D;

    k_setup<<<(HASH_SIZE / 2 + 255) / 256, 256>>>((const unsigned int*)src);
    k_dedup_fill<<<(nE + 255) / 256, 256>>>(src, dst, nE);
    k_agg<<<(nrows + 7) / 8, 256>>>(nfeats, alpha, nrows);
    k_overflow<<<16, 256>>>(nfeats);

    cudaFuncSetAttribute(k_mlp, cudaFuncAttributeMaxDynamicSharedMemorySize,
                         196608);
    int nblk = (nrows + 63) / 64;
    k_mlp<<<nblk, 256, 196608>>>(W1, b1, W2, b2, out, nrows);
}